// round 11
// baseline (speedup 1.0000x reference)
#include <cuda_runtime.h>
#include <cuda_bf16.h>
#include <cstdint>

#define NODES 50000
#define MPAD  50176          // 392 * 128
#define EDIM  128
#define PDIM  768
#define HID   256
#define NREL  16
#define NEDGE 400000
#define BN_EPS 1e-5f
#define MBLK  392            // MPAD / 128
#define SCANB 196
#define PADR  (MPAD - NODES) // 176
#define CATW  768            // concat buffer width (cols)

// ---------------------------------------------------------------------------
// scratch (static device memory; no allocations)
// ---------------------------------------------------------------------------
__device__ __nv_bfloat16 g_cAh[(size_t)MPAD * CATW];   // concat A, bf16-hi
__device__ __nv_bfloat16 g_cAl[(size_t)MPAD * CATW];   // concat A, bf16-lo
__device__ __nv_bfloat16 g_Bth[256 * 768];              // concat B^T hi (K-major)
__device__ __nv_bfloat16 g_Btl[256 * 768];              // concat B^T lo
__device__ float g_fbias[3 * HID];                      // fb0, fb1, fb2(root+bias0)
__device__ float g_svec[MPAD * 2];                      // per-dst s0,s1 (layer0)
__device__ float g_buf[(size_t)MPAD * HID];
__device__ int   g_cnt[NODES * NREL];
__device__ int   g_cntnode[NODES];
__device__ int   g_fill[NODES];
__device__ int   g_rowptr[NODES + 1];
__device__ int   g_blksum[SCANB];
__device__ int   g_packed[NEDGE];
__device__ float g_invw[NEDGE];
__device__ float g_sum[HID], g_sumsq[HID], g_scale[HID], g_shift[HID];

// ---------------------------------------------------------------------------
// helpers
// ---------------------------------------------------------------------------
__device__ __forceinline__ uint32_t smem_u32(const void* p) {
    uint32_t a;
    asm("{ .reg .u64 t; cvta.to.shared.u64 t, %1; cvt.u32.u64 %0, t; }" : "=r"(a) : "l"(p));
    return a;
}
__device__ __forceinline__ void cp16(uint32_t dst, const void* src) {
    asm volatile("cp.async.cg.shared.global [%0], [%1], 16;" :: "r"(dst), "l"(src) : "memory");
}
__device__ __forceinline__ void ldsm4(uint32_t* r, uint32_t addr) {
    asm volatile("ldmatrix.sync.aligned.m8n8.x4.shared.b16 {%0,%1,%2,%3}, [%4];"
                 : "=r"(r[0]), "=r"(r[1]), "=r"(r[2]), "=r"(r[3]) : "r"(addr));
}
__device__ __forceinline__ void mma16816(float* c, const uint32_t* a, const uint32_t* b) {
    asm volatile("mma.sync.aligned.m16n8k16.row.col.f32.bf16.bf16.f32 "
                 "{%0,%1,%2,%3}, {%4,%5,%6,%7}, {%8,%9}, {%0,%1,%2,%3};"
                 : "+f"(c[0]), "+f"(c[1]), "+f"(c[2]), "+f"(c[3])
                 : "r"(a[0]), "r"(a[1]), "r"(a[2]), "r"(a[3]), "r"(b[0]), "r"(b[1]));
}
static __device__ __forceinline__ uint32_t pack_bf2(float a, float b) {
    __nv_bfloat162 t;
    t.x = __float2bfloat16_rn(a);
    t.y = __float2bfloat16_rn(b);
    return *reinterpret_cast<uint32_t*>(&t);
}
__device__ __forceinline__ float2 bf2f(uint32_t u) {
    __nv_bfloat162 b = *reinterpret_cast<__nv_bfloat162*>(&u);
    return make_float2(__bfloat162float(b.x), __bfloat162float(b.y));
}

// chunk-32 layout (round-10 proven): 64B rows padded to 80B
#define ROWB    80
#define A_MAT   10240          // 128*80
#define B_MAT   10240
#define B_BASE  20480
#define STAGEB  40960
#define SMEM_GEMM (2 * STAGEB) // 81920 -> 2 CTAs/SM

// ---------------------------------------------------------------------------
// concat split-bf16 GEMM: buf = A_cat @ B_cat^T + bias (+ rank-2 s·fb terms),
// BN statistics fused into epilogue. CTA 128x128, 256 thr, 2 CTAs/SM.
// grid: x = N/128 (fastest -> A reuse), y = row block.
// ---------------------------------------------------------------------------
__device__ __forceinline__ void load_stage(
    uint32_t sb, int stage, int k0,
    const __nv_bfloat16* __restrict__ Ah, const __nv_bfloat16* __restrict__ Al, int lda,
    const __nv_bfloat16* __restrict__ Bh, const __nv_bfloat16* __restrict__ Bl, int ldb, int t)
{
    uint32_t base = sb + stage * STAGEB;
#pragma unroll
    for (int i = 0; i < 2; i++) {
        int unit = t + i * 256;
        int r = unit >> 2, u = unit & 3;
        uint32_t off = r * ROWB + u * 16;
        cp16(base + off,         Ah + (size_t)r * lda + k0 + u * 8);
        cp16(base + A_MAT + off, Al + (size_t)r * lda + k0 + u * 8);
    }
#pragma unroll
    for (int i = 0; i < 2; i++) {
        int unit = t + i * 256;
        int r = unit >> 2, u = unit & 3;
        uint32_t off = r * ROWB + u * 16;
        cp16(base + B_BASE + off,         Bh + (size_t)r * ldb + k0 + u * 8);
        cp16(base + B_BASE + B_MAT + off, Bl + (size_t)r * ldb + k0 + u * 8);
    }
    asm volatile("cp.async.commit_group;" ::: "memory");
}

__global__ void __launch_bounds__(256, 2) gemm_cat(
    const __nv_bfloat16* __restrict__ Ah, const __nv_bfloat16* __restrict__ Al,
    int K, int lda,
    const __nv_bfloat16* __restrict__ Bth, const __nv_bfloat16* __restrict__ Btl,
    float* __restrict__ C,
    const float* __restrict__ bias,
    const float* __restrict__ sv,      // [MPAD*2] or null
    const float* __restrict__ fb01)    // fb0 | fb1 (2*HID) or null
{
    extern __shared__ char smem[];
    uint32_t sb = smem_u32(smem);
    const int t = threadIdx.x;
    const int w = t >> 5, l = t & 31;
    const int wm = w >> 2, wn = w & 3;
    const int row0 = blockIdx.y * 128;
    const int col0 = blockIdx.x * 128;

    const __nv_bfloat16* A_h = Ah + (size_t)row0 * lda;
    const __nv_bfloat16* A_l = Al + (size_t)row0 * lda;
    const __nv_bfloat16* B_h = Bth + (size_t)col0 * K;
    const __nv_bfloat16* B_l = Btl + (size_t)col0 * K;

    const uint32_t aoff = (uint32_t)((wm * 64 + (l & 15)) * ROWB + (l >> 4) * 16);
    const uint32_t boff = (uint32_t)((wn * 32 + (l & 7) + ((l >> 4) & 1) * 8) * ROWB
                                     + ((l >> 3) & 1) * 16);

    float acc[4][4][4];
#pragma unroll
    for (int mt = 0; mt < 4; mt++)
#pragma unroll
        for (int nt = 0; nt < 4; nt++)
#pragma unroll
            for (int j = 0; j < 4; j++) acc[mt][nt][j] = 0.f;

    const int nch = K >> 5;
    load_stage(sb, 0, 0, A_h, A_l, lda, B_h, B_l, K, t);

    for (int c = 0; c < nch; c++) {
        if (c + 1 < nch) {
            load_stage(sb, (c + 1) & 1, (c + 1) << 5, A_h, A_l, lda, B_h, B_l, K, t);
            asm volatile("cp.async.wait_group 1;" ::: "memory");
        } else {
            asm volatile("cp.async.wait_group 0;" ::: "memory");
        }
        __syncthreads();

        uint32_t Abase = sb + (c & 1) * STAGEB;
        uint32_t Bbase = Abase + B_BASE;
#pragma unroll
        for (int ks = 0; ks < 2; ks++) {
            uint32_t bh[2][4], bl[2][4];
#pragma unroll
            for (int p = 0; p < 2; p++) {
                ldsm4(bh[p], Bbase + boff + p * 1280 + ks * 32);
                ldsm4(bl[p], Bbase + B_MAT + boff + p * 1280 + ks * 32);
            }
#pragma unroll
            for (int mt = 0; mt < 4; mt++) {
                uint32_t ah[4], al[4];
                ldsm4(ah, Abase + aoff + mt * 1280 + ks * 32);
                ldsm4(al, Abase + A_MAT + aoff + mt * 1280 + ks * 32);
#pragma unroll
                for (int nt = 0; nt < 4; nt++) {
                    float* cc = acc[mt][nt];
                    const uint32_t* bph = &bh[nt >> 1][(nt & 1) * 2];
                    const uint32_t* bpl = &bl[nt >> 1][(nt & 1) * 2];
                    mma16816(cc, ah, bph);
                    mma16816(cc, al, bph);
                    mma16816(cc, ah, bpl);
                }
            }
        }
        __syncthreads();
    }

    // epilogue: bias + rank-2 + store + fused BN stats
    const int rl = l >> 2;
    const int cl = (l & 3) * 2;
    float lsum[8], lsq[8];
#pragma unroll
    for (int i = 0; i < 8; i++) { lsum[i] = 0.f; lsq[i] = 0.f; }

#pragma unroll
    for (int mt = 0; mt < 4; mt++) {
#pragma unroll
        for (int rh = 0; rh < 2; rh++) {
            int r = row0 + wm * 64 + mt * 16 + rh * 8 + rl;
            float s0 = 0.f, s1 = 0.f;
            if (sv) { s0 = sv[2 * r]; s1 = sv[2 * r + 1]; }
            bool valid = (r < NODES);
#pragma unroll
            for (int nt = 0; nt < 4; nt++) {
                int cix = col0 + wn * 32 + nt * 8 + cl;
                float v0 = acc[mt][nt][rh * 2 + 0] + bias[cix];
                float v1 = acc[mt][nt][rh * 2 + 1] + bias[cix + 1];
                if (sv) {
                    v0 += s0 * fb01[cix] + s1 * fb01[HID + cix];
                    v1 += s0 * fb01[cix + 1] + s1 * fb01[HID + cix + 1];
                }
                *(float2*)(C + (size_t)r * HID + cix) = make_float2(v0, v1);
                if (valid) {
                    lsum[nt * 2]     += v0; lsq[nt * 2]     += v0 * v0;
                    lsum[nt * 2 + 1] += v1; lsq[nt * 2 + 1] += v1 * v1;
                }
            }
        }
    }
    __syncthreads();                    // smem reuse safe
    float* ssum = (float*)smem;
    float* ssq  = (float*)smem + 128;
    if (t < 128) { ssum[t] = 0.f; ssq[t] = 0.f; }
    __syncthreads();
#pragma unroll
    for (int nt = 0; nt < 4; nt++) {
        int lc = wn * 32 + nt * 8 + cl;
        atomicAdd(&ssum[lc],     lsum[nt * 2]);
        atomicAdd(&ssq[lc],      lsq[nt * 2]);
        atomicAdd(&ssum[lc + 1], lsum[nt * 2 + 1]);
        atomicAdd(&ssq[lc + 1],  lsq[nt * 2 + 1]);
    }
    __syncthreads();
    if (t < 128) {
        atomicAdd(&g_sum[col0 + t], ssum[t]);
        atomicAdd(&g_sumsq[col0 + t], ssq[t]);
    }
}

// ---------------------------------------------------------------------------
// producers
// ---------------------------------------------------------------------------
// normalize emb -> split -> cat cols [256,384)
__global__ void norm_split(const float* __restrict__ emb) {
    int gw = (blockIdx.x * blockDim.x + threadIdx.x) >> 5;
    if (gw >= NODES) return;
    int lane = threadIdx.x & 31;
    float4 v = ((const float4*)(emb + (size_t)gw * EDIM))[lane];
    float ss = v.x * v.x + v.y * v.y + v.z * v.z + v.w * v.w;
#pragma unroll
    for (int o = 16; o > 0; o >>= 1) ss += __shfl_xor_sync(0xffffffffu, ss, o);
    float inv = 1.0f / fmaxf(sqrtf(ss), 1e-12f);
    v.x *= inv; v.y *= inv; v.z *= inv; v.w *= inv;
    __nv_bfloat16 hx = __float2bfloat16_rn(v.x), hy = __float2bfloat16_rn(v.y);
    __nv_bfloat16 hz = __float2bfloat16_rn(v.z), hw = __float2bfloat16_rn(v.w);
    size_t ui = (size_t)gw * (CATW / 2) + 128 + lane * 2;   // col 256 + lane*4
    __nv_bfloat162 p0; p0.x = hx; p0.y = hy;
    __nv_bfloat162 p1; p1.x = hz; p1.y = hw;
    ((uint32_t*)g_cAh)[ui]     = *reinterpret_cast<uint32_t*>(&p0);
    ((uint32_t*)g_cAh)[ui + 1] = *reinterpret_cast<uint32_t*>(&p1);
    ((uint32_t*)g_cAl)[ui]     = pack_bf2(v.x - __bfloat162float(hx), v.y - __bfloat162float(hy));
    ((uint32_t*)g_cAl)[ui + 1] = pack_bf2(v.z - __bfloat162float(hz), v.w - __bfloat162float(hw));
}

__global__ void zero_cat_pads() {
    int n = PADR * CATW / 2;   // uint32 count
    int i = blockIdx.x * blockDim.x + threadIdx.x;
    if (i < n) {
        size_t base = (size_t)NODES * CATW / 2;
        ((uint32_t*)g_cAh)[base + i] = 0;
        ((uint32_t*)g_cAl)[base + i] = 0;
    }
    if (i < PADR * 2) g_svec[NODES * 2 + i] = 0;
}

// layer0 fused weights: F_z = proj_w @ W0_z -> Bt[n*384 + z*128 + e]; fbias.
__global__ void fuse_w(const float* __restrict__ proj_w, const float* __restrict__ proj_b,
                       const float* __restrict__ bases0, const float* __restrict__ root0,
                       const float* __restrict__ bias0) {
    int z = blockIdx.y;
    int idx = blockIdx.x * blockDim.x + threadIdx.x;
    if (idx >= EDIM * HID) return;
    int e = idx >> 8, o = idx & 255;
    const float* W = (z < 2) ? bases0 + (size_t)z * PDIM * HID : root0;
    const float* pw = proj_w + (size_t)e * PDIM;
    float s0 = 0.f, s1 = 0.f, s2 = 0.f, s3 = 0.f;
    for (int p = 0; p < PDIM; p += 4) {
        s0 = fmaf(pw[p + 0], W[(size_t)(p + 0) * HID + o], s0);
        s1 = fmaf(pw[p + 1], W[(size_t)(p + 1) * HID + o], s1);
        s2 = fmaf(pw[p + 2], W[(size_t)(p + 2) * HID + o], s2);
        s3 = fmaf(pw[p + 3], W[(size_t)(p + 3) * HID + o], s3);
    }
    float s = (s0 + s1) + (s2 + s3);
    __nv_bfloat16 h = __float2bfloat16_rn(s);
    size_t off = (size_t)o * 384 + z * 128 + e;
    g_Bth[off] = h;
    g_Btl[off] = __float2bfloat16_rn(s - __bfloat162float(h));
    if (e == 0) {
        float b = 0.f;
        for (int p = 0; p < PDIM; p++) b = fmaf(proj_b[p], W[(size_t)p * HID + o], b);
        if (z == 2) b += bias0[o];
        g_fbias[z * HID + o] = b;
    }
}

// layers 1,2: Bt[n*768 + z*256 + k]
__global__ void split_bt_layer(const float* __restrict__ bases, const float* __restrict__ root) {
    int z = blockIdx.z;
    int idx = blockIdx.x * blockDim.x + threadIdx.x;
    const float* in = (z < 2) ? bases + (size_t)z * HID * HID : root;
    if (idx >= HID * HID) return;
    int k = idx >> 8, n = idx & 255;
    float v = in[idx];
    __nv_bfloat16 h = __float2bfloat16_rn(v);
    size_t o = (size_t)n * 768 + z * 256 + k;
    g_Bth[o] = h;
    g_Btl[o] = __float2bfloat16_rn(v - __bfloat162float(h));
}

// ---------------------------------------------------------------------------
// CSR build
// ---------------------------------------------------------------------------
__global__ void zero_counts() {
    int i = blockIdx.x * blockDim.x + threadIdx.x;
    if (i < NODES * NREL) g_cnt[i] = 0;
    if (i < NODES) { g_cntnode[i] = 0; g_fill[i] = 0; }
}
__global__ void count_edges(const int* __restrict__ dst, const int* __restrict__ et) {
    int e = blockIdx.x * blockDim.x + threadIdx.x;
    if (e < NEDGE) {
        int d = dst[e];
        atomicAdd(&g_cnt[d * NREL + et[e]], 1);
        atomicAdd(&g_cntnode[d], 1);
    }
}
__global__ void scan1() {
    __shared__ int sh[256];
    int t = threadIdx.x;
    int idx = blockIdx.x * 256 + t;
    int v = (idx < NODES) ? g_cntnode[idx] : 0;
    sh[t] = v;
    __syncthreads();
#pragma unroll
    for (int o = 1; o < 256; o <<= 1) {
        int x = (t >= o) ? sh[t - o] : 0;
        __syncthreads();
        sh[t] += x;
        __syncthreads();
    }
    if (idx < NODES) g_rowptr[idx + 1] = sh[t];
    if (t == 255) g_blksum[blockIdx.x] = sh[255];
}
__global__ void scan2() {
    int t = threadIdx.x;
    int carry = 0;
    for (int base = 0; base < SCANB; base += 32) {
        int idx = base + t;
        int vin = (idx < SCANB) ? g_blksum[idx] : 0;
        int v = vin;
#pragma unroll
        for (int o = 1; o < 32; o <<= 1) {
            int x = __shfl_up_sync(0xffffffffu, v, o);
            if (t >= o) v += x;
        }
        if (idx < SCANB) g_blksum[idx] = carry + v - vin;
        carry += __shfl_sync(0xffffffffu, v, 31);
    }
    if (t == 0) g_rowptr[0] = 0;
}
__global__ void scan3() {
    int idx = blockIdx.x * blockDim.x + threadIdx.x;
    if (idx < NODES) g_rowptr[idx + 1] += g_blksum[idx >> 8];
}
__global__ void scatter_edges(const int* __restrict__ src, const int* __restrict__ dst,
                              const int* __restrict__ et) {
    int e = blockIdx.x * blockDim.x + threadIdx.x;
    if (e >= NEDGE) return;
    int d = dst[e], r = et[e], s = src[e];
    int pos = g_rowptr[d] + atomicAdd(&g_fill[d], 1);
    g_packed[pos] = s | (r << 24);
    int c = g_cnt[d * NREL + r];
    g_invw[pos] = 1.0f / (float)(c > 0 ? c : 1);
}

// ---------------------------------------------------------------------------
// aggregate-first: agg_b[d] = sum_e w*c_b * x[src], x read from cat[xoff..),
// results written as bf16 hi/lo into cat cols [0,XC) and [XC,2XC).
// Also writes s0,s1 per dst (layer0) and zeroes BN stat accumulators.
// ---------------------------------------------------------------------------
#define AGG_BLOCKS 1184
template<int XC>
__global__ void __launch_bounds__(256) csr_agg2(const float* __restrict__ comp,
                                                int xoff, int writeS) {
    __shared__ float s_comp[2 * NREL];
    int t = threadIdx.x;
    if (blockIdx.x == 0 && t < HID) { g_sum[t] = 0.f; g_sumsq[t] = 0.f; }
    if (t < 2 * NREL) s_comp[t] = comp[t];
    __syncthreads();
    int lane = t & 31, wid = t >> 5;
    constexpr int NV = XC / 32;       // cols per lane (4 or 8)

    for (int d = blockIdx.x * 8 + wid; d < NODES; d += AGG_BLOCKS * 8) {
        int beg = g_rowptr[d], end = g_rowptr[d + 1];
        float a0[NV], a1[NV];
#pragma unroll
        for (int i = 0; i < NV; i++) { a0[i] = 0.f; a1[i] = 0.f; }
        float sw0 = 0.f, sw1 = 0.f;

        for (int e = beg; e < end; e++) {
            int pk = __ldg(&g_packed[e]);
            float wgt = __ldg(&g_invw[e]);
            int s = pk & 0xFFFFFF;
            int r = pk >> 24;
            float c0 = s_comp[2 * r] * wgt;
            float c1 = s_comp[2 * r + 1] * wgt;
            sw0 += c0; sw1 += c1;
            const uint32_t* ph = (const uint32_t*)(g_cAh + (size_t)s * CATW + xoff);
            const uint32_t* pl = (const uint32_t*)(g_cAl + (size_t)s * CATW + xoff);
#pragma unroll
            for (int j = 0; j < NV / 2; j++) {
                float2 h2 = bf2f(ph[lane * (NV / 2) + j]);
                float2 l2 = bf2f(pl[lane * (NV / 2) + j]);
                float v0 = h2.x + l2.x;
                float v1 = h2.y + l2.y;
                a0[2 * j]     += c0 * v0;
                a0[2 * j + 1] += c0 * v1;
                a1[2 * j]     += c1 * v0;
                a1[2 * j + 1] += c1 * v1;
            }
        }

        // write agg0 -> cols [0,XC), agg1 -> cols [XC,2XC)
        uint32_t* oh = (uint32_t*)(g_cAh + (size_t)d * CATW);
        uint32_t* ol = (uint32_t*)(g_cAl + (size_t)d * CATW);
#pragma unroll
        for (int j = 0; j < NV / 2; j++) {
            float v0 = a0[2 * j], v1 = a0[2 * j + 1];
            __nv_bfloat16 h0 = __float2bfloat16_rn(v0);
            __nv_bfloat16 h1 = __float2bfloat16_rn(v1);
            __nv_bfloat162 hp; hp.x = h0; hp.y = h1;
            oh[lane * (NV / 2) + j] = *reinterpret_cast<uint32_t*>(&hp);
            ol[lane * (NV / 2) + j] = pack_bf2(v0 - __bfloat162float(h0),
                                               v1 - __bfloat162float(h1));
        }
#pragma unroll
        for (int j = 0; j < NV / 2; j++) {
            float v0 = a1[2 * j], v1 = a1[2 * j + 1];
            __nv_bfloat16 h0 = __float2bfloat16_rn(v0);
            __nv_bfloat16 h1 = __float2bfloat16_rn(v1);
            __nv_bfloat162 hp; hp.x = h0; hp.y = h1;
            oh[XC / 2 + lane * (NV / 2) + j] = *reinterpret_cast<uint32_t*>(&hp);
            ol[XC / 2 + lane * (NV / 2) + j] = pack_bf2(v0 - __bfloat162float(h0),
                                                        v1 - __bfloat162float(h1));
        }
        if (writeS && lane == 0) {
            g_svec[2 * d]     = sw0;
            g_svec[2 * d + 1] = sw1;
        }
    }
}

// ---------------------------------------------------------------------------
// batchnorm finalize + apply
// ---------------------------------------------------------------------------
__global__ void bn_finalize(const float* __restrict__ gamma, const float* __restrict__ beta) {
    int c = threadIdx.x;
    const float invM = 1.0f / (float)NODES;
    float mean = g_sum[c] * invM;
    float var = g_sumsq[c] * invM - mean * mean;
    float sc = gamma[c] * rsqrtf(var + BN_EPS);
    g_scale[c] = sc;
    g_shift[c] = beta[c] - mean * sc;
}
__global__ void bn_apply_f32(float* __restrict__ out) {
    int idx = blockIdx.x * blockDim.x + threadIdx.x;
    if (idx >= NODES * HID / 4) return;
    int c4 = (idx & 63) << 2;
    float4 v = ((const float4*)g_buf)[idx];
    float4 sc = *(const float4*)&g_scale[c4];
    float4 sh = *(const float4*)&g_shift[c4];
    v.x = fmaxf(fmaf(v.x, sc.x, sh.x), 0.f);
    v.y = fmaxf(fmaf(v.y, sc.y, sh.y), 0.f);
    v.z = fmaxf(fmaf(v.z, sc.z, sh.z), 0.f);
    v.w = fmaxf(fmaf(v.w, sc.w, sh.w), 0.f);
    ((float4*)out)[idx] = v;
}
// BN+ReLU -> split -> cat cols [512,768)
__global__ void bn_apply_split() {
    int idx = blockIdx.x * blockDim.x + threadIdx.x;
    if (idx >= NODES * HID / 4) return;
    int r = idx >> 6;
    int c4 = (idx & 63) << 2;
    float4 v = ((const float4*)g_buf)[idx];
    float4 sc = *(const float4*)&g_scale[c4];
    float4 sh = *(const float4*)&g_shift[c4];
    v.x = fmaxf(fmaf(v.x, sc.x, sh.x), 0.f);
    v.y = fmaxf(fmaf(v.y, sc.y, sh.y), 0.f);
    v.z = fmaxf(fmaf(v.z, sc.z, sh.z), 0.f);
    v.w = fmaxf(fmaf(v.w, sc.w, sh.w), 0.f);
    __nv_bfloat16 hx = __float2bfloat16_rn(v.x), hy = __float2bfloat16_rn(v.y);
    __nv_bfloat16 hz = __float2bfloat16_rn(v.z), hw = __float2bfloat16_rn(v.w);
    size_t ui = (size_t)r * (CATW / 2) + 256 + (c4 >> 1);   // col 512 + c4
    __nv_bfloat162 p0; p0.x = hx; p0.y = hy;
    __nv_bfloat162 p1; p1.x = hz; p1.y = hw;
    ((uint32_t*)g_cAh)[ui]     = *reinterpret_cast<uint32_t*>(&p0);
    ((uint32_t*)g_cAh)[ui + 1] = *reinterpret_cast<uint32_t*>(&p1);
    ((uint32_t*)g_cAl)[ui]     = pack_bf2(v.x - __bfloat162float(hx), v.y - __bfloat162float(hy));
    ((uint32_t*)g_cAl)[ui + 1] = pack_bf2(v.z - __bfloat162float(hz), v.w - __bfloat162float(hw));
}

// ---------------------------------------------------------------------------
// host launch
// ---------------------------------------------------------------------------
extern "C" void kernel_launch(void* const* d_in, const int* in_sizes, int n_in,
                              void* d_out, int out_size) {
    const int* edge_index = (const int*)d_in[0];
    const int* src = edge_index;
    const int* dst = edge_index + NEDGE;
    const int* etype = (const int*)d_in[1];
    const float* emb = (const float*)d_in[2];
    const float* proj_w = (const float*)d_in[3];
    const float* proj_b = (const float*)d_in[4];

    const float *comp[3], *bases[3], *root[3], *bias[3], *gamma[3], *beta[3];
    for (int l = 0; l < 3; l++) {
        comp[l]  = (const float*)d_in[5 + 6 * l];
        bases[l] = (const float*)d_in[6 + 6 * l];
        root[l]  = (const float*)d_in[7 + 6 * l];
        bias[l]  = (const float*)d_in[8 + 6 * l];
        gamma[l] = (const float*)d_in[9 + 6 * l];
        beta[l]  = (const float*)d_in[10 + 6 * l];
    }

    __nv_bfloat16 *cAh, *cAl, *Bth, *Btl;
    float *buf, *fbias, *svec;
    cudaGetSymbolAddress((void**)&cAh, g_cAh);
    cudaGetSymbolAddress((void**)&cAl, g_cAl);
    cudaGetSymbolAddress((void**)&Bth, g_Bth);
    cudaGetSymbolAddress((void**)&Btl, g_Btl);
    cudaGetSymbolAddress((void**)&buf, g_buf);
    cudaGetSymbolAddress((void**)&fbias, g_fbias);
    cudaGetSymbolAddress((void**)&svec, g_svec);

    cudaFuncSetAttribute(gemm_cat, cudaFuncAttributeMaxDynamicSharedMemorySize, SMEM_GEMM);

    // producers
    norm_split<<<(NODES * 32 + 255) / 256, 256>>>(emb);
    zero_cat_pads<<<(PADR * CATW / 2 + 255) / 256, 256>>>();
    {
        dim3 g((EDIM * HID + 255) / 256, 3);
        fuse_w<<<g, 256>>>(proj_w, proj_b, bases[0], root[0], bias[0]);
    }

    // CSR build
    zero_counts<<<(NODES * NREL + 255) / 256, 256>>>();
    count_edges<<<(NEDGE + 255) / 256, 256>>>(dst, etype);
    scan1<<<SCANB, 256>>>();
    scan2<<<1, 32>>>();
    scan3<<<(NODES + 255) / 256, 256>>>();
    scatter_edges<<<(NEDGE + 255) / 256, 256>>>(src, dst, etype);

    dim3 ggrid(2, MBLK);

    // ---- layer0: agg(xn at col 256, XC=128) -> GEMM K=384 ----
    csr_agg2<128><<<AGG_BLOCKS, 256>>>(comp[0], 256, 1);
    gemm_cat<<<ggrid, 256, SMEM_GEMM>>>(
        cAh, cAl, 384, CATW, Bth, Btl, buf,
        fbias + 2 * HID, svec, fbias);
    bn_finalize<<<1, HID>>>(gamma[0], beta[0]);
    bn_apply_split<<<(NODES * HID / 4 + 255) / 256, 256>>>();

    // ---- layers 1,2: agg(x at col 512, XC=256) -> GEMM K=768 ----
    for (int l = 1; l < 3; l++) {
        {
            dim3 g((HID * HID + 255) / 256, 1, 3);
            split_bt_layer<<<g, 256>>>(bases[l], root[l]);
        }
        csr_agg2<256><<<AGG_BLOCKS, 256>>>(comp[l], 512, 0);
        gemm_cat<<<ggrid, 256, SMEM_GEMM>>>(
            cAh, cAl, 768, CATW, Bth, Btl, buf,
            bias[l], nullptr, nullptr);
        bn_finalize<<<1, HID>>>(gamma[l], beta[l]);
        if (l == 1) bn_apply_split<<<(NODES * HID / 4 + 255) / 256, 256>>>();
        else        bn_apply_f32<<<(NODES * HID / 4 + 255) / 256, 256>>>((float*)d_out);
    }
}